// round 1
// baseline (speedup 1.0000x reference)
#include <cuda_runtime.h>
#include <cuda_bf16.h>
#include <cstdint>

// ---------------------------------------------------------------------------
// PCGen: norm -> conv(16->256,relu) -> conv(256->512,clip,z-mod)
//        -> [conv+BN+relu] x4 (512->512->256->128->64) -> conv(64->3)
//        -> kNN(K=8) graph sharpening filter.
// B=32, M=2048, CW=512.
// ---------------------------------------------------------------------------

#define BATCH 32
#define MPTS  2048
#define CW    512

#define BM 64
#define BN 64
#define BK 16

// ---------------- scratch (static device memory; no allocs allowed) --------
__device__ float g_xn [BATCH * 16  * MPTS];
__device__ float g_y1 [BATCH * 256 * MPTS];
__device__ float g_y2 [BATCH * 512 * MPTS];
__device__ float g_t0 [BATCH * 512 * MPTS];
__device__ float g_t1 [BATCH * 256 * MPTS];
__device__ float g_t2 [BATCH * 128 * MPTS];
__device__ float g_t3 [BATCH * 64  * MPTS];
__device__ float g_pts[BATCH * 3   * MPTS];
__device__ float g_aff_a[4 * 512];
__device__ float g_aff_c[4 * 512];

// ---------------- channel-normalize samples --------------------------------
__global__ void norm_kernel(const float* __restrict__ s, float* __restrict__ xn)
{
    int idx = blockIdx.x * blockDim.x + threadIdx.x;   // over B*M
    if (idx >= BATCH * MPTS) return;
    int b = idx >> 11, m = idx & (MPTS - 1);
    const float* p = s + (size_t)b * 16 * MPTS + m;
    float ss = 0.f;
#pragma unroll
    for (int c = 0; c < 16; ++c) { float v = p[c * MPTS]; ss = fmaf(v, v, ss); }
    float inv = rsqrtf(ss);
    float* q = xn + (size_t)b * 16 * MPTS + m;
#pragma unroll
    for (int c = 0; c < 16; ++c) q[c * MPTS] = p[c * MPTS] * inv;
}

// ---------------- tiled fp32 GEMM with fused prologue/epilogue --------------
// Y[b][o][m] = sum_k W[o][k] * f(X[b][k][m]) + bias[o], then epilogue.
// PRO=1: f(x) = relu(pa[k]*x + pc[k])   (folded BN + relu of previous layer)
// EPI=0: none ; EPI=1: relu ; EPI=2: z[b][o] * clamp(v, -1, 1)
template <int PRO, int EPI>
__global__ void gemm_kernel(const float* __restrict__ X,
                            const float* __restrict__ W,
                            const float* __restrict__ bias,
                            float* __restrict__ Y,
                            int Cin, int Cout,
                            const float* __restrict__ pa,
                            const float* __restrict__ pc,
                            const float* __restrict__ zmod)
{
    int b  = blockIdx.z;
    const float* Xb = X + (size_t)b * Cin  * MPTS;
    float*       Yb = Y + (size_t)b * Cout * MPTS;
    int n0 = blockIdx.x * BN;
    int o0 = blockIdx.y * BM;

    __shared__ float Ws[BM][BK + 1];                 // padded: conflict-free
    __shared__ __align__(16) float Xs[BK][BN];

    int tid = threadIdx.x;                           // 256 threads
    int tx = tid & 15;                               // m-tile lane
    int ty = tid >> 4;                               // o-tile lane

    float acc[4][4] = {};

    for (int k0 = 0; k0 < Cin; k0 += BK) {
        // W tile: BM x BK (coalesced reads, consecutive k per thread group)
#pragma unroll
        for (int i = tid; i < BM * BK; i += 256) {
            int o = i >> 4, k = i & 15;
            Ws[o][k] = W[(size_t)(o0 + o) * Cin + k0 + k];
        }
        // X tile: BK x BN with optional BN-affine+relu prologue
#pragma unroll
        for (int i = tid; i < BK * BN; i += 256) {
            int k = i >> 6, n = i & 63;
            float v = Xb[(size_t)(k0 + k) * MPTS + n0 + n];
            if (PRO) v = fmaxf(fmaf(pa[k0 + k], v, pc[k0 + k]), 0.f);
            Xs[k][n] = v;
        }
        __syncthreads();

#pragma unroll
        for (int k = 0; k < BK; ++k) {
            float4 xr = *(const float4*)&Xs[k][tx * 4];
            float wr[4];
#pragma unroll
            for (int i = 0; i < 4; ++i) wr[i] = Ws[ty * 4 + i][k];
#pragma unroll
            for (int i = 0; i < 4; ++i) {
                acc[i][0] = fmaf(wr[i], xr.x, acc[i][0]);
                acc[i][1] = fmaf(wr[i], xr.y, acc[i][1]);
                acc[i][2] = fmaf(wr[i], xr.z, acc[i][2]);
                acc[i][3] = fmaf(wr[i], xr.w, acc[i][3]);
            }
        }
        __syncthreads();
    }

#pragma unroll
    for (int i = 0; i < 4; ++i) {
        int o = o0 + ty * 4 + i;
        float bs = bias[o];
        float zv = (EPI == 2) ? zmod[(size_t)b * CW + o] : 0.f;
#pragma unroll
        for (int j = 0; j < 4; ++j) {
            float v = acc[i][j] + bs;
            if (EPI == 1) v = fmaxf(v, 0.f);
            if (EPI == 2) v = zv * fminf(fmaxf(v, -1.f), 1.f);
            Yb[(size_t)o * MPTS + n0 + tx * 4 + j] = v;
        }
    }
}

// ---------------- BN stats -> folded affine (a, c) --------------------------
__global__ void bn_stats_kernel(const float* __restrict__ T, int Cout,
                                const float* __restrict__ g,
                                const float* __restrict__ be,
                                float* __restrict__ a_out,
                                float* __restrict__ c_out)
{
    int o = blockIdx.x;
    const int NTOT = BATCH * MPTS;
    float s = 0.f, s2 = 0.f;
    for (int i = threadIdx.x; i < NTOT; i += blockDim.x) {
        int b = i >> 11, m = i & (MPTS - 1);
        float v = T[((size_t)b * Cout + o) * MPTS + m];
        s += v;
        s2 = fmaf(v, v, s2);
    }
#pragma unroll
    for (int off = 16; off; off >>= 1) {
        s  += __shfl_down_sync(0xffffffffu, s,  off);
        s2 += __shfl_down_sync(0xffffffffu, s2, off);
    }
    __shared__ float sh[8], sh2[8];
    int w = threadIdx.x >> 5, l = threadIdx.x & 31;
    if (l == 0) { sh[w] = s; sh2[w] = s2; }
    __syncthreads();
    if (threadIdx.x < 8) {
        s = sh[threadIdx.x]; s2 = sh2[threadIdx.x];
#pragma unroll
        for (int off = 4; off; off >>= 1) {
            s  += __shfl_down_sync(0xffu, s,  off);
            s2 += __shfl_down_sync(0xffu, s2, off);
        }
        if (threadIdx.x == 0) {
            const float inv = 1.f / (float)NTOT;
            float mu  = s * inv;
            float var = s2 * inv - mu * mu;
            float aa  = g[o] * rsqrtf(var + 1e-5f);
            a_out[o] = aa;
            c_out[o] = be[o] - aa * mu;
        }
    }
}

// ---------------- final 64->3 projection with folded BN+relu ----------------
__global__ void out_kernel(const float* __restrict__ T3,
                           const float* __restrict__ w_out,
                           const float* __restrict__ b_out,
                           const float* __restrict__ a,
                           const float* __restrict__ c,
                           float* __restrict__ pts)
{
    __shared__ float Ws[3][64];
    __shared__ float As[64], Cs[64];
    int tid = threadIdx.x;
    if (tid < 192) Ws[tid / 64][tid & 63] = w_out[tid];
    if (tid < 64) { As[tid] = a[tid]; Cs[tid] = c[tid]; }
    __syncthreads();

    int idx = blockIdx.x * blockDim.x + tid;
    int b = idx >> 11, m = idx & (MPTS - 1);
    const float* p = T3 + (size_t)b * 64 * MPTS + m;
    float a0 = b_out[0], a1 = b_out[1], a2 = b_out[2];
#pragma unroll 8
    for (int k = 0; k < 64; ++k) {
        float v = fmaxf(fmaf(As[k], p[(size_t)k * MPTS], Cs[k]), 0.f);
        a0 = fmaf(Ws[0][k], v, a0);
        a1 = fmaf(Ws[1][k], v, a1);
        a2 = fmaf(Ws[2][k], v, a2);
    }
    float* q = pts + (size_t)b * 3 * MPTS + m;
    q[0]        = a0;
    q[MPTS]     = a1;
    q[2 * MPTS] = a2;
}

// ---------------- kNN (K=8) sharpening filter -------------------------------
__global__ void graph_filter_kernel(const float* __restrict__ pts,
                                    float* __restrict__ out)
{
    __shared__ float sx[MPTS], sy[MPTS], sz[MPTS], sq[MPTS];
    int b = blockIdx.y;
    int tid = threadIdx.x;                         // 256
    const float* pb = pts + (size_t)b * 3 * MPTS;
    for (int i = tid; i < MPTS; i += 256) {
        float x = pb[i], y = pb[MPTS + i], z = pb[2 * MPTS + i];
        sx[i] = x; sy[i] = y; sz[i] = z;
        sq[i] = x * x + y * y + z * z;
    }
    __syncthreads();

    int p = blockIdx.x * 256 + tid;
    float px = sx[p], py = sy[p], pz = sz[p], psq = sq[p];

    float bd[8]; int bi[8];
#pragma unroll
    for (int j = 0; j < 8; ++j) { bd[j] = 3.4e38f; bi[j] = 0; }

    for (int n = 0; n < MPTS; ++n) {
        float d = psq + sq[n]
                - 2.f * (px * sx[n] + py * sy[n] + pz * sz[n]);
        if (n != p && d < bd[7]) {
            bd[7] = d; bi[7] = n;
#pragma unroll
            for (int j = 7; j > 0; --j) {
                if (bd[j] < bd[j - 1]) {
                    float td = bd[j]; bd[j] = bd[j - 1]; bd[j - 1] = td;
                    int   ti = bi[j]; bi[j] = bi[j - 1]; bi[j - 1] = ti;
                }
            }
        }
    }

    float mx = 0.f, my = 0.f, mz = 0.f;
#pragma unroll
    for (int j = 0; j < 8; ++j) {
        mx += sx[bi[j]]; my += sy[bi[j]]; mz += sz[bi[j]];
    }
    const float k8 = 1.f / 8.f;
    float* ob = out + (size_t)b * 3 * MPTS;
    ob[p]            = 2.f * px - mx * k8;
    ob[MPTS + p]     = 2.f * py - my * k8;
    ob[2 * MPTS + p] = 2.f * pz - mz * k8;
}

// ---------------------------------------------------------------------------
extern "C" void kernel_launch(void* const* d_in, const int* in_sizes, int n_in,
                              void* d_out, int out_size)
{
    const float* z     = (const float*)d_in[0];
    const float* s     = (const float*)d_in[1];
    const float* w_m1  = (const float*)d_in[2];
    const float* b_m1  = (const float*)d_in[3];
    const float* w_m2  = (const float*)d_in[4];
    const float* b_m2  = (const float*)d_in[5];
    const float* w_out = (const float*)d_in[6];
    const float* b_out = (const float*)d_in[7];
    const float* w_c [4] = {(const float*)d_in[8],  (const float*)d_in[12],
                            (const float*)d_in[16], (const float*)d_in[20]};
    const float* b_c [4] = {(const float*)d_in[9],  (const float*)d_in[13],
                            (const float*)d_in[17], (const float*)d_in[21]};
    const float* g_c [4] = {(const float*)d_in[10], (const float*)d_in[14],
                            (const float*)d_in[18], (const float*)d_in[22]};
    const float* be_c[4] = {(const float*)d_in[11], (const float*)d_in[15],
                            (const float*)d_in[19], (const float*)d_in[23]};

    float *xn, *y1, *y2, *t0, *t1, *t2, *t3, *pts, *aff_a, *aff_c;
    cudaGetSymbolAddress((void**)&xn,    g_xn);
    cudaGetSymbolAddress((void**)&y1,    g_y1);
    cudaGetSymbolAddress((void**)&y2,    g_y2);
    cudaGetSymbolAddress((void**)&t0,    g_t0);
    cudaGetSymbolAddress((void**)&t1,    g_t1);
    cudaGetSymbolAddress((void**)&t2,    g_t2);
    cudaGetSymbolAddress((void**)&t3,    g_t3);
    cudaGetSymbolAddress((void**)&pts,   g_pts);
    cudaGetSymbolAddress((void**)&aff_a, g_aff_a);
    cudaGetSymbolAddress((void**)&aff_c, g_aff_c);

    // 1) normalize samples
    norm_kernel<<<(BATCH * MPTS) / 256, 256>>>(s, xn);

    // 2) map_samples1: 16 -> 256, relu
    gemm_kernel<0, 1><<<dim3(MPTS / BN, 256 / BM, BATCH), 256>>>(
        xn, w_m1, b_m1, y1, 16, 256, nullptr, nullptr, nullptr);

    // 3) map_samples2: 256 -> 512, clip(-1,1) then z-mod
    gemm_kernel<0, 2><<<dim3(MPTS / BN, 512 / BM, BATCH), 256>>>(
        y1, w_m2, b_m2, y2, 256, 512, nullptr, nullptr, z);

    // 4) conv block 0: 512 -> 512 (+bias), stats
    gemm_kernel<0, 0><<<dim3(MPTS / BN, 512 / BM, BATCH), 256>>>(
        y2, w_c[0], b_c[0], t0, 512, 512, nullptr, nullptr, nullptr);
    bn_stats_kernel<<<512, 256>>>(t0, 512, g_c[0], be_c[0], aff_a, aff_c);

    // 5) conv block 1: relu(bn(t0)) -> 256
    gemm_kernel<1, 0><<<dim3(MPTS / BN, 256 / BM, BATCH), 256>>>(
        t0, w_c[1], b_c[1], t1, 512, 256, aff_a, aff_c, nullptr);
    bn_stats_kernel<<<256, 256>>>(t1, 256, g_c[1], be_c[1],
                                  aff_a + 512, aff_c + 512);

    // 6) conv block 2: -> 128
    gemm_kernel<1, 0><<<dim3(MPTS / BN, 128 / BM, BATCH), 256>>>(
        t1, w_c[2], b_c[2], t2, 256, 128, aff_a + 512, aff_c + 512, nullptr);
    bn_stats_kernel<<<128, 256>>>(t2, 128, g_c[2], be_c[2],
                                  aff_a + 1024, aff_c + 1024);

    // 7) conv block 3: -> 64
    gemm_kernel<1, 0><<<dim3(MPTS / BN, 64 / BM, BATCH), 256>>>(
        t2, w_c[3], b_c[3], t3, 128, 64, aff_a + 1024, aff_c + 1024, nullptr);
    bn_stats_kernel<<<64, 256>>>(t3, 64, g_c[3], be_c[3],
                                 aff_a + 1536, aff_c + 1536);

    // 8) output projection 64 -> 3 (with folded BN+relu)
    out_kernel<<<(BATCH * MPTS) / 256, 256>>>(t3, w_out, b_out,
                                              aff_a + 1536, aff_c + 1536, pts);

    // 9) graph sharpening filter
    graph_filter_kernel<<<dim3(MPTS / 256, BATCH), 256>>>(pts, (float*)d_out);
}